// round 7
// baseline (speedup 1.0000x reference)
#include <cuda_runtime.h>
#include <cstdint>
#include <cstddef>

// Problem constants
#define BB 4096
#define SS 128
#define DD 256
#define CC 5

#define ROWS 32            // batch rows per CTA
#define NTHREADS 512       // 16 warps = 4 row-groups (8 rows) x 4 j-quarters (64 cols)
#define NGRID (BB / ROWS)  // 128 CTAs
#define HS 36              // padded stride (floats) of k-major SMEM tiles
#define KK (2 * DD)        // fused K dimension: [xe ; h]

// Fused transposed weights [512][256]: rows 0..255 = W_ih^T, rows 256..511 = W_hh^T.
__device__ __align__(16) float g_W[KK * DD];
__device__ __align__(16) float g_bias[DD];   // b_ih + b_hh

// ---------- f32x2 packed-FMA helpers (sm_103a) ----------
__device__ __forceinline__ unsigned long long pack2(float x, float y) {
    unsigned long long r;
    asm("mov.b64 %0, {%1,%2};" : "=l"(r) : "f"(x), "f"(y));
    return r;
}
__device__ __forceinline__ void fma2(unsigned long long& d, unsigned long long a, unsigned long long b) {
    asm("fma.rn.f32x2 %0, %1, %2, %0;" : "+l"(d) : "l"(a), "l"(b));
}
__device__ __forceinline__ float2 unpack2(unsigned long long v) {
    float2 r;
    asm("mov.b64 {%0,%1}, %2;" : "=f"(r.x), "=f"(r.y) : "l"(v));
    return r;
}

// Fast accurate tanh: 1 - 2/(e^{2x}+1). Clamp keeps __fdividef in safe range.
// abs err ~1e-6 (EX2 ~2^-21 rel, fast div ~2 ulp) — far inside 1e-3 budget.
__device__ __forceinline__ float fast_tanh(float x) {
    x = fminf(fmaxf(x, -10.0f), 10.0f);
    float e = __expf(2.0f * x);
    return 1.0f - __fdividef(2.0f, e + 1.0f);
}

// ---------- prep: transpose+concat weights, fuse biases ----------
__global__ void prep_kernel(const float* __restrict__ W_ih,
                            const float* __restrict__ W_hh,
                            const float* __restrict__ b_ih,
                            const float* __restrict__ b_hh) {
    int k = blockIdx.x;   // 0..511
    int j = threadIdx.x;  // 0..255
    if (k < DD) g_W[k * DD + j] = W_ih[j * DD + k];
    else        g_W[k * DD + j] = W_hh[j * DD + (k - DD)];
    if (k == 0) g_bias[j] = b_ih[j] + b_hh[j];
}

// ---------- fused persistent RNN kernel ----------
// SMEM (floats):
//   ab_s [KK][HS]  k-major fused tile: rows 0..255 = xe(t), rows 256..511 = h(t)
//   tok  [ROWS][SS] int tokens, loaded once
#define SMEM_FLOATS (KK * HS + ROWS * SS)
#define SMEM_BYTES  (SMEM_FLOATS * 4)

__global__ void __launch_bounds__(NTHREADS, 1)
rnn_kernel(const int* __restrict__ x,          // int32 (JAX x64-disabled)
           const float* __restrict__ emb,
           const float* __restrict__ W_cls,
           const float* __restrict__ b_cls,
           float* __restrict__ out) {
    extern __shared__ float smem[];
    float* ab_s  = smem;                       // KK*HS  (xe rows 0..255, h rows 256..511)
    int*   tok_s = (int*)(smem + KK * HS);     // ROWS*SS

    const int tid  = threadIdx.x;
    const int lane = tid & 31;
    const int warp = tid >> 5;
    const int row0 = blockIdx.x * ROWS;

    // warp tile: 8 rows x 64 cols; thread tile: 8 rows x 2 cols
    const int r0 = (warp >> 2) * 8;                 // 0,8,16,24
    const int j0 = (warp & 3) * 64 + lane * 2;      // 2-col slice

    // gather mapping: 16 threads per row, 4 float4 chunks each
    const int g_row = tid >> 4;     // 0..31
    const int g_sub = tid & 15;

    // ---- one-time init: tokens + zero hidden region ----
    for (int idx = tid; idx < ROWS * SS; idx += NTHREADS) {
        int r = idx >> 7;
        int t = idx & (SS - 1);
        tok_s[idx] = x[(size_t)(row0 + r) * SS + t];
    }
    for (int idx = tid; idx < DD * HS; idx += NTHREADS) ab_s[DD * HS + idx] = 0.0f;

    // bias pairs: acc pair = (row r, row r+1) of SAME col -> (b[j], b[j])
    const float2 b2 = *(const float2*)(g_bias + j0);
    const unsigned long long bp0 = pack2(b2.x, b2.x);
    const unsigned long long bp1 = pack2(b2.y, b2.y);

    __syncthreads();   // tok_s + h-zero visible

    // ---- prologue: gather xe(0) into regs, commit to SMEM ----
    float4 xr[4];
    {
        int tok = tok_s[g_row * SS + 0];
        const float* erow = emb + (size_t)tok * DD;
        #pragma unroll
        for (int i = 0; i < 4; i++) xr[i] = *(const float4*)(erow + i * 64 + g_sub * 4);
    }
    #pragma unroll
    for (int i = 0; i < 4; i++) {
        int c0 = i * 64 + g_sub * 4;
        ab_s[(c0 + 0) * HS + g_row] = xr[i].x;
        ab_s[(c0 + 1) * HS + g_row] = xr[i].y;
        ab_s[(c0 + 2) * HS + g_row] = xr[i].z;
        ab_s[(c0 + 3) * HS + g_row] = xr[i].w;
    }
    __syncthreads();

    for (int t = 0; t < SS; t++) {
        // ---- prefetch xe(t+1) into regs (overlaps with GEMM below) ----
        {
            int tn = (t + 1 < SS) ? (t + 1) : t;
            int tok = tok_s[g_row * SS + tn];
            const float* erow = emb + (size_t)tok * DD;
            #pragma unroll
            for (int i = 0; i < 4; i++) xr[i] = *(const float4*)(erow + i * 64 + g_sub * 4);
        }

        // ---- fused GEMM: pre = bias + [xe;h] @ [Wt_ih;Wt_hh] ----
        // acc[p][c]: row-pair p (r0+2p, r0+2p+1), col j0+c
        unsigned long long acc[4][2];
        #pragma unroll
        for (int p = 0; p < 4; p++) { acc[p][0] = bp0; acc[p][1] = bp1; }

        #pragma unroll 8
        for (int k = 0; k < KK; k++) {
            float2 w = *(const float2*)(g_W + (k << 8) + j0);         // 1 LDG.64 (2 wf/warp)
            ulonglong2 aA = *(const ulonglong2*)(ab_s + k * HS + r0);     // rows r0..r0+3
            ulonglong2 aB = *(const ulonglong2*)(ab_s + k * HS + r0 + 4); // rows r0+4..r0+7
            unsigned long long w0 = pack2(w.x, w.x);
            unsigned long long w1 = pack2(w.y, w.y);
            fma2(acc[0][0], aA.x, w0); fma2(acc[0][1], aA.x, w1);
            fma2(acc[1][0], aA.y, w0); fma2(acc[1][1], aA.y, w1);
            fma2(acc[2][0], aB.x, w0); fma2(acc[2][1], aB.x, w1);
            fma2(acc[3][0], aB.y, w0); fma2(acc[3][1], aB.y, w1);
        }

        // ---- tanh (register-only, before the barrier) ----
        float hv[2][8];   // hv[c][rr] : col c, rows r0..r0+7
        #pragma unroll
        for (int c = 0; c < 2; c++) {
            #pragma unroll
            for (int p = 0; p < 4; p++) {
                float2 v = unpack2(acc[p][c]);
                hv[c][2 * p]     = fast_tanh(v.x);
                hv[c][2 * p + 1] = fast_tanh(v.y);
            }
        }

        __syncthreads();   // all reads of ab_s (xe & h) complete

        // ---- commit new h (k-major) + xe(t+1) ----
        #pragma unroll
        for (int c = 0; c < 2; c++) {
            float* dst = ab_s + (DD + j0 + c) * HS + r0;
            *(float4*)(dst)     = make_float4(hv[c][0], hv[c][1], hv[c][2], hv[c][3]);
            *(float4*)(dst + 4) = make_float4(hv[c][4], hv[c][5], hv[c][6], hv[c][7]);
        }
        #pragma unroll
        for (int i = 0; i < 4; i++) {
            int c0 = i * 64 + g_sub * 4;
            ab_s[(c0 + 0) * HS + g_row] = xr[i].x;
            ab_s[(c0 + 1) * HS + g_row] = xr[i].y;
            ab_s[(c0 + 2) * HS + g_row] = xr[i].z;
            ab_s[(c0 + 3) * HS + g_row] = xr[i].w;
        }
        __syncthreads();   // writes visible for next step
    }

    // ---- classifier: out[r][c] = b_cls[c] + sum_d h[r][d] * W_cls[c][d] ----
    if (tid < ROWS * CC) {
        int r = tid / CC;
        int c = tid % CC;
        float s = b_cls[c];
        const float* wc = W_cls + c * DD;
        #pragma unroll 8
        for (int d = 0; d < DD; d++) {
            s += ab_s[(DD + d) * HS + r] * wc[d];
        }
        out[(size_t)(row0 + r) * CC + c] = s;
    }
}

extern "C" void kernel_launch(void* const* d_in, const int* in_sizes, int n_in,
                              void* d_out, int out_size) {
    const int* x         = (const int*)d_in[0];   // int32
    const float* emb     = (const float*)d_in[1];
    const float* W_ih    = (const float*)d_in[2];
    const float* W_hh    = (const float*)d_in[3];
    const float* b_ih    = (const float*)d_in[4];
    const float* b_hh    = (const float*)d_in[5];
    const float* W_cls   = (const float*)d_in[6];
    const float* b_cls   = (const float*)d_in[7];
    float* out = (float*)d_out;

    (void)in_sizes; (void)n_in; (void)out_size;

    cudaFuncSetAttribute(rnn_kernel, cudaFuncAttributeMaxDynamicSharedMemorySize, SMEM_BYTES);

    prep_kernel<<<KK, DD>>>(W_ih, W_hh, b_ih, b_hh);
    rnn_kernel<<<NGRID, NTHREADS, SMEM_BYTES>>>(x, emb, W_cls, b_cls, out);
}

// round 8
// speedup vs baseline: 1.0655x; 1.0655x over previous
#include <cuda_runtime.h>
#include <cstdint>
#include <cstddef>

// Problem constants
#define BB 4096
#define SS 128
#define DD 256
#define CC 5

#define ROWS 32            // batch rows per CTA
#define NTHREADS 512       // 16 warps = 8 row-groups (4 rows) x 2 j-halves (128 cols)
#define NGRID (BB / ROWS)  // 128 CTAs
#define HS 36              // padded stride (floats) of k-major SMEM tiles
#define KK (2 * DD)        // fused K dimension: [xe ; h]

// Fused transposed weights [512][256]: rows 0..255 = W_ih^T, rows 256..511 = W_hh^T.
__device__ __align__(16) float g_W[KK * DD];
__device__ __align__(16) float g_bias[DD];   // b_ih + b_hh

// ---------- f32x2 packed-FMA helpers (sm_103a) ----------
__device__ __forceinline__ unsigned long long pack2(float x, float y) {
    unsigned long long r;
    asm("mov.b64 %0, {%1,%2};" : "=l"(r) : "f"(x), "f"(y));
    return r;
}
__device__ __forceinline__ void fma2(unsigned long long& d, unsigned long long a, unsigned long long b) {
    asm("fma.rn.f32x2 %0, %1, %2, %0;" : "+l"(d) : "l"(a), "l"(b));
}
__device__ __forceinline__ float2 unpack2(unsigned long long v) {
    float2 r;
    asm("mov.b64 {%0,%1}, %2;" : "=f"(r.x), "=f"(r.y) : "l"(v));
    return r;
}

// Fast accurate tanh: 1 - 2/(e^{2x}+1). abs err ~1e-6, far inside 1e-3 budget.
__device__ __forceinline__ float fast_tanh(float x) {
    x = fminf(fmaxf(x, -10.0f), 10.0f);
    float e = __expf(2.0f * x);
    return 1.0f - __fdividef(2.0f, e + 1.0f);
}

// ---------- prep: transpose+concat weights, fuse biases ----------
__global__ void prep_kernel(const float* __restrict__ W_ih,
                            const float* __restrict__ W_hh,
                            const float* __restrict__ b_ih,
                            const float* __restrict__ b_hh) {
    int k = blockIdx.x;   // 0..511
    int j = threadIdx.x;  // 0..255
    if (k < DD) g_W[k * DD + j] = W_ih[j * DD + k];
    else        g_W[k * DD + j] = W_hh[j * DD + (k - DD)];
    if (k == 0) g_bias[j] = b_ih[j] + b_hh[j];
}

// ---------- fused persistent RNN kernel (double-buffered, 1 barrier/step) ----------
// SMEM (floats):
//   buf0 [KK][HS], buf1 [KK][HS] : k-major fused tiles (xe rows 0..255, h rows 256..511)
//   tok  [ROWS][SS] int tokens, loaded once
#define BUF_FLOATS (KK * HS)
#define SMEM_FLOATS (2 * BUF_FLOATS + ROWS * SS)
#define SMEM_BYTES  (SMEM_FLOATS * 4)

__global__ void __launch_bounds__(NTHREADS, 1)
rnn_kernel(const int* __restrict__ x,          // int32 (JAX x64-disabled)
           const float* __restrict__ emb,
           const float* __restrict__ W_cls,
           const float* __restrict__ b_cls,
           float* __restrict__ out) {
    extern __shared__ float smem[];
    float* buf0  = smem;                           // KK*HS
    float* buf1  = smem + BUF_FLOATS;              // KK*HS
    int*   tok_s = (int*)(smem + 2 * BUF_FLOATS);  // ROWS*SS

    const int tid  = threadIdx.x;
    const int lane = tid & 31;
    const int warp = tid >> 5;
    const int row0 = blockIdx.x * ROWS;

    // warp tile: 4 rows x 128 cols; thread tile: 4 rows x 4 cols
    const int r0 = (warp >> 1) * 4;                  // 0,4,...,28
    const int j0 = (warp & 1) * 128 + lane * 4;

    // gather mapping: 16 threads per row, 4 float4 chunks each
    const int g_row = tid >> 4;     // 0..31
    const int g_sub = tid & 15;

    // ---- one-time init: tokens + zero hidden region of buf0 ----
    for (int idx = tid; idx < ROWS * SS; idx += NTHREADS) {
        int r = idx >> 7;
        int t = idx & (SS - 1);
        tok_s[idx] = x[(size_t)(row0 + r) * SS + t];
    }
    for (int idx = tid; idx < DD * HS; idx += NTHREADS) buf0[DD * HS + idx] = 0.0f;

    // bias pairs: acc pair = (row r, row r+1) of SAME col -> (b[j], b[j])
    const float4 b4 = *(const float4*)(g_bias + j0);
    unsigned long long bp[4];
    bp[0] = pack2(b4.x, b4.x);
    bp[1] = pack2(b4.y, b4.y);
    bp[2] = pack2(b4.z, b4.z);
    bp[3] = pack2(b4.w, b4.w);

    __syncthreads();   // tok_s visible

    // ---- prologue: gather xe(0) into regs, commit to buf0 ----
    float4 xr[4];
    {
        int tok = tok_s[g_row * SS + 0];
        const float* erow = emb + (size_t)tok * DD;
        #pragma unroll
        for (int i = 0; i < 4; i++) xr[i] = *(const float4*)(erow + i * 64 + g_sub * 4);
    }
    #pragma unroll
    for (int i = 0; i < 4; i++) {
        int c0 = i * 64 + g_sub * 4;
        buf0[(c0 + 0) * HS + g_row] = xr[i].x;
        buf0[(c0 + 1) * HS + g_row] = xr[i].y;
        buf0[(c0 + 2) * HS + g_row] = xr[i].z;
        buf0[(c0 + 3) * HS + g_row] = xr[i].w;
    }
    __syncthreads();

    for (int t = 0; t < SS; t++) {
        float* cur = (t & 1) ? buf1 : buf0;
        float* nxt = (t & 1) ? buf0 : buf1;

        // ---- prefetch xe(t+1) into regs (overlaps GEMM) ----
        {
            int tn = (t + 1 < SS) ? (t + 1) : t;
            int tok = tok_s[g_row * SS + tn];
            const float* erow = emb + (size_t)tok * DD;
            #pragma unroll
            for (int i = 0; i < 4; i++) xr[i] = *(const float4*)(erow + i * 64 + g_sub * 4);
        }

        // ---- fused GEMM: pre = bias + [xe;h] @ [Wt_ih;Wt_hh] ----
        unsigned long long acc[2][4];
        acc[0][0] = bp[0]; acc[0][1] = bp[1]; acc[0][2] = bp[2]; acc[0][3] = bp[3];
        acc[1][0] = bp[0]; acc[1][1] = bp[1]; acc[1][2] = bp[2]; acc[1][3] = bp[3];

        #pragma unroll 8
        for (int k = 0; k < KK; k++) {
            float4 w = *(const float4*)(g_W + (k << 8) + j0);        // 1 LDG.128
            ulonglong2 a = *(const ulonglong2*)(cur + k * HS + r0);  // LDS.128 broadcast: rows r0..r0+3
            unsigned long long w0 = pack2(w.x, w.x);
            unsigned long long w1 = pack2(w.y, w.y);
            unsigned long long w2 = pack2(w.z, w.z);
            unsigned long long w3 = pack2(w.w, w.w);
            fma2(acc[0][0], a.x, w0); fma2(acc[0][1], a.x, w1);
            fma2(acc[0][2], a.x, w2); fma2(acc[0][3], a.x, w3);
            fma2(acc[1][0], a.y, w0); fma2(acc[1][1], a.y, w1);
            fma2(acc[1][2], a.y, w2); fma2(acc[1][3], a.y, w3);
        }

        // ---- tanh (register-only) ----
        float hv[4][4];   // hv[c][rr] : col c, rows r0..r0+3
        #pragma unroll
        for (int c = 0; c < 4; c++) {
            float2 v0 = unpack2(acc[0][c]);
            float2 v1 = unpack2(acc[1][c]);
            hv[c][0] = fast_tanh(v0.x);
            hv[c][1] = fast_tanh(v0.y);
            hv[c][2] = fast_tanh(v1.x);
            hv[c][3] = fast_tanh(v1.y);
        }

        // ---- commit h(t+1) + xe(t+1) into NEXT buffer (no barrier needed before) ----
        #pragma unroll
        for (int c = 0; c < 4; c++) {
            *(float4*)(nxt + (DD + j0 + c) * HS + r0) =
                make_float4(hv[c][0], hv[c][1], hv[c][2], hv[c][3]);
        }
        #pragma unroll
        for (int i = 0; i < 4; i++) {
            int c0 = i * 64 + g_sub * 4;
            nxt[(c0 + 0) * HS + g_row] = xr[i].x;
            nxt[(c0 + 1) * HS + g_row] = xr[i].y;
            nxt[(c0 + 2) * HS + g_row] = xr[i].z;
            nxt[(c0 + 3) * HS + g_row] = xr[i].w;
        }
        __syncthreads();   // nxt complete AND all reads of cur done (one barrier/step)
    }

    // ---- classifier: last h written by t=127 into buf0 ----
    if (tid < ROWS * CC) {
        int r = tid / CC;
        int c = tid % CC;
        float s = b_cls[c];
        const float* wc = W_cls + c * DD;
        #pragma unroll 8
        for (int d = 0; d < DD; d++) {
            s += buf0[(DD + d) * HS + r] * wc[d];
        }
        out[(size_t)(row0 + r) * CC + c] = s;
    }
}

extern "C" void kernel_launch(void* const* d_in, const int* in_sizes, int n_in,
                              void* d_out, int out_size) {
    const int* x         = (const int*)d_in[0];   // int32
    const float* emb     = (const float*)d_in[1];
    const float* W_ih    = (const float*)d_in[2];
    const float* W_hh    = (const float*)d_in[3];
    const float* b_ih    = (const float*)d_in[4];
    const float* b_hh    = (const float*)d_in[5];
    const float* W_cls   = (const float*)d_in[6];
    const float* b_cls   = (const float*)d_in[7];
    float* out = (float*)d_out;

    (void)in_sizes; (void)n_in; (void)out_size;

    cudaFuncSetAttribute(rnn_kernel, cudaFuncAttributeMaxDynamicSharedMemorySize, SMEM_BYTES);

    prep_kernel<<<KK, DD>>>(W_ih, W_hh, b_ih, b_hh);
    rnn_kernel<<<NGRID, NTHREADS, SMEM_BYTES>>>(x, emb, W_cls, b_cls, out);
}

// round 9
// speedup vs baseline: 1.1334x; 1.0637x over previous
#include <cuda_runtime.h>
#include <cstdint>
#include <cstddef>

// Problem constants
#define BB 4096
#define SS 128
#define DD 256
#define CC 5

#define ROWS 32            // batch rows per CTA
#define NTHREADS 256       // 8 warps = 4 row-groups (8 rows) x 2 j-halves (128 cols)
#define NGRID (BB / ROWS)  // 128 CTAs
#define HS 36              // padded stride (floats) of k-major SMEM tiles
#define KK (2 * DD)        // fused K dimension: [xe ; h]

// Fused transposed weights [512][256]: rows 0..255 = W_ih^T, rows 256..511 = W_hh^T.
__device__ __align__(16) float g_W[KK * DD];
__device__ __align__(16) float g_bias[DD];   // b_ih + b_hh

// ---------- f32x2 packed-FMA helpers (sm_103a) ----------
__device__ __forceinline__ unsigned long long pack2(float x, float y) {
    unsigned long long r;
    asm("mov.b64 %0, {%1,%2};" : "=l"(r) : "f"(x), "f"(y));
    return r;
}
__device__ __forceinline__ void fma2(unsigned long long& d, unsigned long long a, unsigned long long b) {
    asm("fma.rn.f32x2 %0, %1, %2, %0;" : "+l"(d) : "l"(a), "l"(b));
}
__device__ __forceinline__ float2 unpack2(unsigned long long v) {
    float2 r;
    asm("mov.b64 {%0,%1}, %2;" : "=f"(r.x), "=f"(r.y) : "l"(v));
    return r;
}

// Fast accurate tanh: 1 - 2/(e^{2x}+1). abs err ~1e-6, far inside 1e-3 budget.
__device__ __forceinline__ float fast_tanh(float x) {
    x = fminf(fmaxf(x, -10.0f), 10.0f);
    float e = __expf(2.0f * x);
    return 1.0f - __fdividef(2.0f, e + 1.0f);
}

// ---------- prep: transpose+concat weights, fuse biases ----------
__global__ void prep_kernel(const float* __restrict__ W_ih,
                            const float* __restrict__ W_hh,
                            const float* __restrict__ b_ih,
                            const float* __restrict__ b_hh) {
    int k = blockIdx.x;   // 0..511
    int j = threadIdx.x;  // 0..255
    if (k < DD) g_W[k * DD + j] = W_ih[j * DD + k];
    else        g_W[k * DD + j] = W_hh[j * DD + (k - DD)];
    if (k == 0) g_bias[j] = b_ih[j] + b_hh[j];
}

// ---------- fused persistent RNN kernel (double-buffered, 1 barrier/step) ----------
// SMEM (floats):
//   buf0 [KK][HS], buf1 [KK][HS] : k-major fused tiles (xe rows 0..255, h rows 256..511)
//   tok  [ROWS][SS] int tokens, loaded once
#define BUF_FLOATS (KK * HS)
#define SMEM_FLOATS (2 * BUF_FLOATS + ROWS * SS)
#define SMEM_BYTES  (SMEM_FLOATS * 4)

__global__ void __launch_bounds__(NTHREADS, 1)
rnn_kernel(const int* __restrict__ x,          // int32 (JAX x64-disabled)
           const float* __restrict__ emb,
           const float* __restrict__ W_cls,
           const float* __restrict__ b_cls,
           float* __restrict__ out) {
    extern __shared__ float smem[];
    float* buf0  = smem;                           // KK*HS
    float* buf1  = smem + BUF_FLOATS;              // KK*HS
    int*   tok_s = (int*)(smem + 2 * BUF_FLOATS);  // ROWS*SS

    const int tid  = threadIdx.x;
    const int lane = tid & 31;
    const int warp = tid >> 5;
    const int row0 = blockIdx.x * ROWS;

    // warp tile: 8 rows x 128 cols; thread tile: 8 rows x 4 cols (16 fma2/k)
    const int r0 = (warp >> 1) * 8;                  // 0,8,16,24
    const int j0 = (warp & 1) * 128 + lane * 4;

    // gather mapping: 8 threads per row, 8 float4 chunks each
    const int g_row = tid >> 3;     // 0..31
    const int g_sub = tid & 7;

    // ---- one-time init: tokens + zero hidden region of buf0 ----
    for (int idx = tid; idx < ROWS * SS; idx += NTHREADS) {
        int r = idx >> 7;
        int t = idx & (SS - 1);
        tok_s[idx] = x[(size_t)(row0 + r) * SS + t];
    }
    for (int idx = tid; idx < DD * HS; idx += NTHREADS) buf0[DD * HS + idx] = 0.0f;

    // bias pairs: acc pair = (row r, row r+1) of SAME col -> (b[j], b[j])
    const float4 b4 = *(const float4*)(g_bias + j0);
    unsigned long long bp[4];
    bp[0] = pack2(b4.x, b4.x);
    bp[1] = pack2(b4.y, b4.y);
    bp[2] = pack2(b4.z, b4.z);
    bp[3] = pack2(b4.w, b4.w);

    __syncthreads();   // tok_s visible

    // ---- prologue: gather xe(0) into regs, commit to buf0 ----
    float4 xr[8];
    {
        int tok = tok_s[g_row * SS + 0];
        const float* erow = emb + (size_t)tok * DD;
        #pragma unroll
        for (int i = 0; i < 8; i++) xr[i] = *(const float4*)(erow + i * 32 + g_sub * 4);
    }
    #pragma unroll
    for (int i = 0; i < 8; i++) {
        int c0 = i * 32 + g_sub * 4;
        buf0[(c0 + 0) * HS + g_row] = xr[i].x;
        buf0[(c0 + 1) * HS + g_row] = xr[i].y;
        buf0[(c0 + 2) * HS + g_row] = xr[i].z;
        buf0[(c0 + 3) * HS + g_row] = xr[i].w;
    }
    __syncthreads();

    for (int t = 0; t < SS; t++) {
        float* cur = (t & 1) ? buf1 : buf0;
        float* nxt = (t & 1) ? buf0 : buf1;

        // ---- prefetch xe(t+1) into regs (overlaps GEMM) ----
        {
            int tn = (t + 1 < SS) ? (t + 1) : t;
            int tok = tok_s[g_row * SS + tn];
            const float* erow = emb + (size_t)tok * DD;
            #pragma unroll
            for (int i = 0; i < 8; i++) xr[i] = *(const float4*)(erow + i * 32 + g_sub * 4);
        }

        // ---- fused GEMM: pre = bias + [xe;h] @ [Wt_ih;Wt_hh] ----
        // acc[p][c]: row-pair p covers rows (r0+2p, r0+2p+1), col j0+c
        unsigned long long acc[4][4];
        #pragma unroll
        for (int p = 0; p < 4; p++) {
            acc[p][0] = bp[0]; acc[p][1] = bp[1]; acc[p][2] = bp[2]; acc[p][3] = bp[3];
        }

        #pragma unroll 8
        for (int k = 0; k < KK; k++) {
            float4 w = *(const float4*)(g_W + (k << 8) + j0);            // 1 LDG.128
            ulonglong2 aA = *(const ulonglong2*)(cur + k * HS + r0);     // rows r0..r0+3
            ulonglong2 aB = *(const ulonglong2*)(cur + k * HS + r0 + 4); // rows r0+4..r0+7
            unsigned long long w0 = pack2(w.x, w.x);
            unsigned long long w1 = pack2(w.y, w.y);
            unsigned long long w2 = pack2(w.z, w.z);
            unsigned long long w3 = pack2(w.w, w.w);
            fma2(acc[0][0], aA.x, w0); fma2(acc[0][1], aA.x, w1);
            fma2(acc[0][2], aA.x, w2); fma2(acc[0][3], aA.x, w3);
            fma2(acc[1][0], aA.y, w0); fma2(acc[1][1], aA.y, w1);
            fma2(acc[1][2], aA.y, w2); fma2(acc[1][3], aA.y, w3);
            fma2(acc[2][0], aB.x, w0); fma2(acc[2][1], aB.x, w1);
            fma2(acc[2][2], aB.x, w2); fma2(acc[2][3], aB.x, w3);
            fma2(acc[3][0], aB.y, w0); fma2(acc[3][1], aB.y, w1);
            fma2(acc[3][2], aB.y, w2); fma2(acc[3][3], aB.y, w3);
        }

        // ---- tanh (register-only) ----
        float hv[4][8];   // hv[c][rr] : col c, rows r0..r0+7
        #pragma unroll
        for (int c = 0; c < 4; c++) {
            #pragma unroll
            for (int p = 0; p < 4; p++) {
                float2 v = unpack2(acc[p][c]);
                hv[c][2 * p]     = fast_tanh(v.x);
                hv[c][2 * p + 1] = fast_tanh(v.y);
            }
        }

        // ---- commit h(t+1) + xe(t+1) into NEXT buffer ----
        #pragma unroll
        for (int c = 0; c < 4; c++) {
            float* dst = nxt + (DD + j0 + c) * HS + r0;
            *(float4*)(dst)     = make_float4(hv[c][0], hv[c][1], hv[c][2], hv[c][3]);
            *(float4*)(dst + 4) = make_float4(hv[c][4], hv[c][5], hv[c][6], hv[c][7]);
        }
        #pragma unroll
        for (int i = 0; i < 8; i++) {
            int c0 = i * 32 + g_sub * 4;
            nxt[(c0 + 0) * HS + g_row] = xr[i].x;
            nxt[(c0 + 1) * HS + g_row] = xr[i].y;
            nxt[(c0 + 2) * HS + g_row] = xr[i].z;
            nxt[(c0 + 3) * HS + g_row] = xr[i].w;
        }
        __syncthreads();   // nxt complete AND all reads of cur done (one barrier/step)
    }

    // ---- classifier: last h written by t=127 into buf0 ----
    if (tid < ROWS * CC) {
        int r = tid / CC;
        int c = tid % CC;
        float s = b_cls[c];
        const float* wc = W_cls + c * DD;
        #pragma unroll 8
        for (int d = 0; d < DD; d++) {
            s += buf0[(DD + d) * HS + r] * wc[d];
        }
        out[(size_t)(row0 + r) * CC + c] = s;
    }
}

extern "C" void kernel_launch(void* const* d_in, const int* in_sizes, int n_in,
                              void* d_out, int out_size) {
    const int* x         = (const int*)d_in[0];   // int32
    const float* emb     = (const float*)d_in[1];
    const float* W_ih    = (const float*)d_in[2];
    const float* W_hh    = (const float*)d_in[3];
    const float* b_ih    = (const float*)d_in[4];
    const float* b_hh    = (const float*)d_in[5];
    const float* W_cls   = (const float*)d_in[6];
    const float* b_cls   = (const float*)d_in[7];
    float* out = (float*)d_out;

    (void)in_sizes; (void)n_in; (void)out_size;

    cudaFuncSetAttribute(rnn_kernel, cudaFuncAttributeMaxDynamicSharedMemorySize, SMEM_BYTES);

    prep_kernel<<<KK, DD>>>(W_ih, W_hh, b_ih, b_hh);
    rnn_kernel<<<NGRID, NTHREADS, SMEM_BYTES>>>(x, emb, W_cls, b_cls, out);
}

// round 10
// speedup vs baseline: 1.2838x; 1.1327x over previous
#include <cuda_runtime.h>
#include <cstdint>
#include <cstddef>

// Problem constants
#define BB 4096
#define SS 128
#define DD 256
#define CC 5

#define ROWS 32            // batch rows per CTA
#define NTHREADS 256       // 8 warps = 4 row-groups (8 rows) x 2 j-halves (128 cols)
#define NGRID (BB / ROWS)  // 128 CTAs
#define HS 36              // padded stride (floats) of k-major SMEM tiles
#define KK (2 * DD)        // fused K dimension: [xe ; h]
#define KB 8               // k-block size for weight pipeline
#define NKB (KK / KB)      // 64 blocks

// Fused transposed weights [512][256]: rows 0..255 = W_ih^T, rows 256..511 = W_hh^T.
__device__ __align__(16) float g_W[KK * DD];
__device__ __align__(16) float g_bias[DD];   // b_ih + b_hh

// ---------- f32x2 packed-FMA helpers (sm_103a) ----------
__device__ __forceinline__ unsigned long long pack2(float x, float y) {
    unsigned long long r;
    asm("mov.b64 %0, {%1,%2};" : "=l"(r) : "f"(x), "f"(y));
    return r;
}
__device__ __forceinline__ void fma2(unsigned long long& d, unsigned long long a, unsigned long long b) {
    asm("fma.rn.f32x2 %0, %1, %2, %0;" : "+l"(d) : "l"(a), "l"(b));
}
__device__ __forceinline__ float2 unpack2(unsigned long long v) {
    float2 r;
    asm("mov.b64 {%0,%1}, %2;" : "=f"(r.x), "=f"(r.y) : "l"(v));
    return r;
}

// Fast accurate tanh: 1 - 2/(e^{2x}+1). abs err ~1e-6, far inside 1e-3 budget.
__device__ __forceinline__ float fast_tanh(float x) {
    x = fminf(fmaxf(x, -10.0f), 10.0f);
    float e = __expf(2.0f * x);
    return 1.0f - __fdividef(2.0f, e + 1.0f);
}

// ---------- prep: transpose+concat weights, fuse biases ----------
__global__ void prep_kernel(const float* __restrict__ W_ih,
                            const float* __restrict__ W_hh,
                            const float* __restrict__ b_ih,
                            const float* __restrict__ b_hh) {
    int k = blockIdx.x;   // 0..511
    int j = threadIdx.x;  // 0..255
    if (k < DD) g_W[k * DD + j] = W_ih[j * DD + k];
    else        g_W[k * DD + j] = W_hh[j * DD + (k - DD)];
    if (k == 0) g_bias[j] = b_ih[j] + b_hh[j];
}

// ---------- fused persistent RNN kernel (double-buffered, 1 barrier/step) ----------
// SMEM (floats):
//   buf0 [KK][HS], buf1 [KK][HS] : k-major fused tiles (xe rows 0..255, h rows 256..511)
//   tok  [ROWS][SS] int tokens, loaded once
#define BUF_FLOATS (KK * HS)
#define SMEM_FLOATS (2 * BUF_FLOATS + ROWS * SS)
#define SMEM_BYTES  (SMEM_FLOATS * 4)

__global__ void __launch_bounds__(NTHREADS, 1)
rnn_kernel(const int* __restrict__ x,          // int32 (JAX x64-disabled)
           const float* __restrict__ emb,
           const float* __restrict__ W_cls,
           const float* __restrict__ b_cls,
           float* __restrict__ out) {
    extern __shared__ float smem[];
    float* buf0  = smem;                           // KK*HS
    float* buf1  = smem + BUF_FLOATS;              // KK*HS
    int*   tok_s = (int*)(smem + 2 * BUF_FLOATS);  // ROWS*SS

    const int tid  = threadIdx.x;
    const int lane = tid & 31;
    const int warp = tid >> 5;
    const int row0 = blockIdx.x * ROWS;

    // warp tile: 8 rows x 128 cols; thread tile: 8 rows x 4 cols (16 fma2/k)
    const int r0 = (warp >> 1) * 8;                  // 0,8,16,24
    const int j0 = (warp & 1) * 128 + lane * 4;

    // gather mapping: 8 threads per row, 8 float4 chunks each
    const int g_row = tid >> 3;     // 0..31
    const int g_sub = tid & 7;

    // ---- one-time init: tokens + zero hidden region of buf0 ----
    for (int idx = tid; idx < ROWS * SS; idx += NTHREADS) {
        int r = idx >> 7;
        int t = idx & (SS - 1);
        tok_s[idx] = x[(size_t)(row0 + r) * SS + t];
    }
    for (int idx = tid; idx < DD * HS; idx += NTHREADS) buf0[DD * HS + idx] = 0.0f;

    // bias pairs: acc pair = (row r, row r+1) of SAME col -> (b[j], b[j])
    const float4 b4 = *(const float4*)(g_bias + j0);
    unsigned long long bp[4];
    bp[0] = pack2(b4.x, b4.x);
    bp[1] = pack2(b4.y, b4.y);
    bp[2] = pack2(b4.z, b4.z);
    bp[3] = pack2(b4.w, b4.w);

    __syncthreads();   // tok_s visible

    // ---- prologue: gather xe(0), commit to buf0 ----
    {
        int tok = tok_s[g_row * SS + 0];
        const float* erow = emb + (size_t)tok * DD;
        #pragma unroll
        for (int i = 0; i < 8; i++) {
            float4 v = *(const float4*)(erow + i * 32 + g_sub * 4);
            int c0 = i * 32 + g_sub * 4;
            buf0[(c0 + 0) * HS + g_row] = v.x;
            buf0[(c0 + 1) * HS + g_row] = v.y;
            buf0[(c0 + 2) * HS + g_row] = v.z;
            buf0[(c0 + 3) * HS + g_row] = v.w;
        }
    }
    __syncthreads();

    const float* wbase = g_W + j0;

    for (int t = 0; t < SS; t++) {
        float* cur = (t & 1) ? buf1 : buf0;
        float* nxt = (t & 1) ? buf0 : buf1;

        // ---- accumulators ----
        unsigned long long acc[4][4];
        #pragma unroll
        for (int p = 0; p < 4; p++) {
            acc[p][0] = bp[0]; acc[p][1] = bp[1]; acc[p][2] = bp[2]; acc[p][3] = bp[3];
        }

        // ---- software-pipelined fused GEMM over k-blocks of 8 ----
        float4 wc[KB], wn[KB];
        #pragma unroll
        for (int i = 0; i < KB; i++) wc[i] = *(const float4*)(wbase + i * DD);

        #pragma unroll 2
        for (int kb = 0; kb < NKB; kb++) {
            // prefetch next block's weights (kb=63 re-reads own block; L1-hit, harmless)
            const float* wnx = wbase + ((kb + 1 < NKB) ? (kb + 1) : kb) * (KB * DD);
            #pragma unroll
            for (int i = 0; i < KB; i++) wn[i] = *(const float4*)(wnx + i * DD);

            const float* abase = cur + (kb * KB) * HS + r0;
            #pragma unroll
            for (int i = 0; i < KB; i++) {
                ulonglong2 aA = *(const ulonglong2*)(abase + i * HS);     // rows r0..r0+3
                ulonglong2 aB = *(const ulonglong2*)(abase + i * HS + 4); // rows r0+4..r0+7
                unsigned long long w0 = pack2(wc[i].x, wc[i].x);
                unsigned long long w1 = pack2(wc[i].y, wc[i].y);
                unsigned long long w2 = pack2(wc[i].z, wc[i].z);
                unsigned long long w3 = pack2(wc[i].w, wc[i].w);
                fma2(acc[0][0], aA.x, w0); fma2(acc[0][1], aA.x, w1);
                fma2(acc[0][2], aA.x, w2); fma2(acc[0][3], aA.x, w3);
                fma2(acc[1][0], aA.y, w0); fma2(acc[1][1], aA.y, w1);
                fma2(acc[1][2], aA.y, w2); fma2(acc[1][3], aA.y, w3);
                fma2(acc[2][0], aB.x, w0); fma2(acc[2][1], aB.x, w1);
                fma2(acc[2][2], aB.x, w2); fma2(acc[2][3], aB.x, w3);
                fma2(acc[3][0], aB.y, w0); fma2(acc[3][1], aB.y, w1);
                fma2(acc[3][2], aB.y, w2); fma2(acc[3][3], aB.y, w3);
            }
            #pragma unroll
            for (int i = 0; i < KB; i++) wc[i] = wn[i];   // renamed away by ptxas (unroll 2)
        }

        // ---- gather xe(t+1) (latency hides under tanh below) ----
        float4 xr[8];
        {
            int tn = (t + 1 < SS) ? (t + 1) : t;
            int tok = tok_s[g_row * SS + tn];
            const float* erow = emb + (size_t)tok * DD;
            #pragma unroll
            for (int i = 0; i < 8; i++) xr[i] = *(const float4*)(erow + i * 32 + g_sub * 4);
        }

        // ---- tanh (register-only) ----
        float hv[4][8];   // hv[c][rr] : col c, rows r0..r0+7
        #pragma unroll
        for (int c = 0; c < 4; c++) {
            #pragma unroll
            for (int p = 0; p < 4; p++) {
                float2 v = unpack2(acc[p][c]);
                hv[c][2 * p]     = fast_tanh(v.x);
                hv[c][2 * p + 1] = fast_tanh(v.y);
            }
        }

        // ---- commit h(t+1) + xe(t+1) into NEXT buffer ----
        #pragma unroll
        for (int c = 0; c < 4; c++) {
            float* dst = nxt + (DD + j0 + c) * HS + r0;
            *(float4*)(dst)     = make_float4(hv[c][0], hv[c][1], hv[c][2], hv[c][3]);
            *(float4*)(dst + 4) = make_float4(hv[c][4], hv[c][5], hv[c][6], hv[c][7]);
        }
        #pragma unroll
        for (int i = 0; i < 8; i++) {
            int c0 = i * 32 + g_sub * 4;
            nxt[(c0 + 0) * HS + g_row] = xr[i].x;
            nxt[(c0 + 1) * HS + g_row] = xr[i].y;
            nxt[(c0 + 2) * HS + g_row] = xr[i].z;
            nxt[(c0 + 3) * HS + g_row] = xr[i].w;
        }
        __syncthreads();   // nxt complete AND all reads of cur done (one barrier/step)
    }

    // ---- classifier: last h written by t=127 into buf0 ----
    if (tid < ROWS * CC) {
        int r = tid / CC;
        int c = tid % CC;
        float s = b_cls[c];
        const float* wc2 = W_cls + c * DD;
        #pragma unroll 8
        for (int d = 0; d < DD; d++) {
            s += buf0[(DD + d) * HS + r] * wc2[d];
        }
        out[(size_t)(row0 + r) * CC + c] = s;
    }
}

extern "C" void kernel_launch(void* const* d_in, const int* in_sizes, int n_in,
                              void* d_out, int out_size) {
    const int* x         = (const int*)d_in[0];   // int32
    const float* emb     = (const float*)d_in[1];
    const float* W_ih    = (const float*)d_in[2];
    const float* W_hh    = (const float*)d_in[3];
    const float* b_ih    = (const float*)d_in[4];
    const float* b_hh    = (const float*)d_in[5];
    const float* W_cls   = (const float*)d_in[6];
    const float* b_cls   = (const float*)d_in[7];
    float* out = (float*)d_out;

    (void)in_sizes; (void)n_in; (void)out_size;

    cudaFuncSetAttribute(rnn_kernel, cudaFuncAttributeMaxDynamicSharedMemorySize, SMEM_BYTES);

    prep_kernel<<<KK, DD>>>(W_ih, W_hh, b_ih, b_hh);
    rnn_kernel<<<NGRID, NTHREADS, SMEM_BYTES>>>(x, emb, W_cls, b_cls, out);
}

// round 11
// speedup vs baseline: 2.0665x; 1.6097x over previous
#include <cuda_runtime.h>
#include <cstdint>
#include <cstddef>

// Problem constants
#define VOCAB 50000
#define BB 4096
#define SS 128
#define DD 256
#define CC 5

#define ROWS 32            // batch rows per CTA
#define NTHREADS 256       // 8 warps = 4 row-groups (8 rows) x 2 j-halves (128 cols)
#define NGRID (BB / ROWS)  // 128 CTAs
#define HS 36              // padded stride (floats) of k-major SMEM tiles
#define KB 8               // k-block size for weight pipeline

// Device globals (static allocation only).
__device__ __align__(16) float g_Whh_t[DD * DD];   // Whh_t[k][j] = W_hh[j][k]
__device__ __align__(16) float g_Wih_t[DD * DD];   // Wih_t[k][j] = W_ih[j][k]
__device__ __align__(16) float g_bias[DD];         // b_ih + b_hh
__device__ __align__(16) float g_E2[VOCAB * DD];   // E' = emb @ W_ih^T  (51.2 MB)

// ---------- f32x2 packed-FMA helpers (sm_103a) ----------
__device__ __forceinline__ unsigned long long pack2(float x, float y) {
    unsigned long long r;
    asm("mov.b64 %0, {%1,%2};" : "=l"(r) : "f"(x), "f"(y));
    return r;
}
__device__ __forceinline__ void fma2(unsigned long long& d, unsigned long long a, unsigned long long b) {
    asm("fma.rn.f32x2 %0, %1, %2, %0;" : "+l"(d) : "l"(a), "l"(b));
}
__device__ __forceinline__ float2 unpack2(unsigned long long v) {
    float2 r;
    asm("mov.b64 {%0,%1}, %2;" : "=f"(r.x), "=f"(r.y) : "l"(v));
    return r;
}

// Fast accurate tanh: 1 - 2/(e^{2x}+1). abs err ~1e-6, far inside 1e-3 budget.
__device__ __forceinline__ float fast_tanh(float x) {
    x = fminf(fmaxf(x, -10.0f), 10.0f);
    float e = __expf(2.0f * x);
    return 1.0f - __fdividef(2.0f, e + 1.0f);
}

// ---------- prep1: transpose weights, fuse biases ----------
__global__ void prep_kernel(const float* __restrict__ W_ih,
                            const float* __restrict__ W_hh,
                            const float* __restrict__ b_ih,
                            const float* __restrict__ b_hh) {
    int k = blockIdx.x;   // 0..255
    int j = threadIdx.x;  // 0..255
    g_Whh_t[k * DD + j] = W_hh[j * DD + k];
    g_Wih_t[k * DD + j] = W_ih[j * DD + k];
    if (k == 0) g_bias[j] = b_ih[j] + b_hh[j];
}

// ---------- prep2: E' = emb @ W_ih^T  ([VOCAB,256] x [256,256]) ----------
// Same tile machinery as the RNN GEMM: 32 vocab rows/CTA, 8 warps,
// warp = 8 rows x 128 cols, thread = 8 rows x 4 cols.
#define PGRID ((VOCAB + ROWS - 1) / ROWS)   // 1563

__global__ void __launch_bounds__(NTHREADS, 1)
egemm_kernel(const float* __restrict__ emb) {
    __shared__ float xe_s[DD * HS];   // k-major emb tile

    const int tid  = threadIdx.x;
    const int lane = tid & 31;
    const int warp = tid >> 5;
    const int v0   = blockIdx.x * ROWS;

    const int r0 = (warp >> 1) * 8;
    const int j0 = (warp & 1) * 128 + lane * 4;
    const int g_row = tid >> 3;
    const int g_sub = tid & 7;

    // gather emb tile (clamp OOB rows to 0; emb[0] is the zero pad row anyway)
    {
        int v = v0 + g_row;
        if (v >= VOCAB) v = 0;
        const float* erow = emb + (size_t)v * DD;
        #pragma unroll
        for (int i = 0; i < 8; i++) {
            float4 vv = *(const float4*)(erow + i * 32 + g_sub * 4);
            int c0 = i * 32 + g_sub * 4;
            xe_s[(c0 + 0) * HS + g_row] = vv.x;
            xe_s[(c0 + 1) * HS + g_row] = vv.y;
            xe_s[(c0 + 2) * HS + g_row] = vv.z;
            xe_s[(c0 + 3) * HS + g_row] = vv.w;
        }
    }
    __syncthreads();

    unsigned long long acc[4][4];
    const unsigned long long z = pack2(0.0f, 0.0f);
    #pragma unroll
    for (int p = 0; p < 4; p++) {
        acc[p][0] = z; acc[p][1] = z; acc[p][2] = z; acc[p][3] = z;
    }

    const float* wbase = g_Wih_t + j0;
    float4 wc[KB], wn[KB];
    #pragma unroll
    for (int i = 0; i < KB; i++) wc[i] = *(const float4*)(wbase + i * DD);

    #pragma unroll 2
    for (int kb = 0; kb < DD / KB; kb++) {
        const float* wnx = wbase + ((kb + 1 < DD / KB) ? (kb + 1) : kb) * (KB * DD);
        #pragma unroll
        for (int i = 0; i < KB; i++) wn[i] = *(const float4*)(wnx + i * DD);

        const float* abase = xe_s + (kb * KB) * HS + r0;
        #pragma unroll
        for (int i = 0; i < KB; i++) {
            ulonglong2 aA = *(const ulonglong2*)(abase + i * HS);
            ulonglong2 aB = *(const ulonglong2*)(abase + i * HS + 4);
            unsigned long long w0 = pack2(wc[i].x, wc[i].x);
            unsigned long long w1 = pack2(wc[i].y, wc[i].y);
            unsigned long long w2 = pack2(wc[i].z, wc[i].z);
            unsigned long long w3 = pack2(wc[i].w, wc[i].w);
            fma2(acc[0][0], aA.x, w0); fma2(acc[0][1], aA.x, w1);
            fma2(acc[0][2], aA.x, w2); fma2(acc[0][3], aA.x, w3);
            fma2(acc[1][0], aA.y, w0); fma2(acc[1][1], aA.y, w1);
            fma2(acc[1][2], aA.y, w2); fma2(acc[1][3], aA.y, w3);
            fma2(acc[2][0], aB.x, w0); fma2(acc[2][1], aB.x, w1);
            fma2(acc[2][2], aB.x, w2); fma2(acc[2][3], aB.x, w3);
            fma2(acc[3][0], aB.y, w0); fma2(acc[3][1], aB.y, w1);
            fma2(acc[3][2], aB.y, w2); fma2(acc[3][3], aB.y, w3);
        }
        #pragma unroll
        for (int i = 0; i < KB; i++) wc[i] = wn[i];
    }

    // write: per row-pair p, rows v0+r0+2p(+1), cols j0..j0+3 (one float4 each)
    #pragma unroll
    for (int p = 0; p < 4; p++) {
        float2 v0c = unpack2(acc[p][0]);
        float2 v1c = unpack2(acc[p][1]);
        float2 v2c = unpack2(acc[p][2]);
        float2 v3c = unpack2(acc[p][3]);
        int va = v0 + r0 + 2 * p;
        int vb = va + 1;
        if (va < VOCAB)
            *(float4*)(g_E2 + (size_t)va * DD + j0) = make_float4(v0c.x, v1c.x, v2c.x, v3c.x);
        if (vb < VOCAB)
            *(float4*)(g_E2 + (size_t)vb * DD + j0) = make_float4(v0c.y, v1c.y, v2c.y, v3c.y);
    }
}

// ---------- fused persistent RNN kernel (K=256 recurrence only) ----------
// SMEM (floats):
//   buf0 [DD][HS], buf1 [DD][HS] : k-major hidden-state tiles
//   tok  [ROWS][SS] int tokens, loaded once
#define BUF_FLOATS (DD * HS)
#define SMEM_FLOATS (2 * BUF_FLOATS + ROWS * SS)
#define SMEM_BYTES  (SMEM_FLOATS * 4)

__global__ void __launch_bounds__(NTHREADS, 1)
rnn_kernel(const int* __restrict__ x,          // int32 (JAX x64-disabled)
           const float* __restrict__ W_cls,
           const float* __restrict__ b_cls,
           float* __restrict__ out) {
    extern __shared__ float smem[];
    float* buf0  = smem;                           // DD*HS
    float* buf1  = smem + BUF_FLOATS;              // DD*HS
    int*   tok_s = (int*)(smem + 2 * BUF_FLOATS);  // ROWS*SS

    const int tid  = threadIdx.x;
    const int lane = tid & 31;
    const int warp = tid >> 5;
    const int row0 = blockIdx.x * ROWS;

    // warp tile: 8 rows x 128 cols; thread tile: 8 rows x 4 cols (16 fma2/k)
    const int r0 = (warp >> 1) * 8;                  // 0,8,16,24
    const int j0 = (warp & 1) * 128 + lane * 4;

    // ---- one-time init: tokens + zero h in buf0 ----
    for (int idx = tid; idx < ROWS * SS; idx += NTHREADS) {
        int r = idx >> 7;
        int t = idx & (SS - 1);
        tok_s[idx] = x[(size_t)(row0 + r) * SS + t];
    }
    for (int idx = tid; idx < BUF_FLOATS; idx += NTHREADS) buf0[idx] = 0.0f;

    // bias pairs + unit multiplier (bias applied via fma2 at epilogue)
    const float4 b4 = *(const float4*)(g_bias + j0);
    unsigned long long bp[4];
    bp[0] = pack2(b4.x, b4.x);
    bp[1] = pack2(b4.y, b4.y);
    bp[2] = pack2(b4.z, b4.z);
    bp[3] = pack2(b4.w, b4.w);
    const unsigned long long ONE2 = pack2(1.0f, 1.0f);

    __syncthreads();   // tok_s + h-zero visible

    // ---- prologue: gather E'[tok(0)] rows for this thread's 8 rows x 4 cols ----
    float4 xr[8];
    #pragma unroll
    for (int i = 0; i < 8; i++) {
        int tokr = tok_s[(r0 + i) * SS + 0];
        xr[i] = *(const float4*)(g_E2 + (size_t)tokr * DD + j0);
    }

    const float* wbase = g_Whh_t + j0;

    for (int t = 0; t < SS; t++) {
        float* cur = (t & 1) ? buf1 : buf0;
        float* nxt = (t & 1) ? buf0 : buf1;

        // ---- acc init from E'[tok(t)] (xr consumed here, regs freed) ----
        unsigned long long acc[4][4];
        #pragma unroll
        for (int p = 0; p < 4; p++) {
            acc[p][0] = pack2(xr[2 * p].x, xr[2 * p + 1].x);
            acc[p][1] = pack2(xr[2 * p].y, xr[2 * p + 1].y);
            acc[p][2] = pack2(xr[2 * p].z, xr[2 * p + 1].z);
            acc[p][3] = pack2(xr[2 * p].w, xr[2 * p + 1].w);
        }

        // ---- prefetch E'[tok(t+1)] (latency hidden under the whole GEMM) ----
        {
            int tn = (t + 1 < SS) ? (t + 1) : t;
            #pragma unroll
            for (int i = 0; i < 8; i++) {
                int tokr = tok_s[(r0 + i) * SS + tn];
                xr[i] = *(const float4*)(g_E2 + (size_t)tokr * DD + j0);
            }
        }

        // ---- software-pipelined GEMM: acc += h @ Whh^T  (K=256) ----
        float4 wc[KB], wn[KB];
        #pragma unroll
        for (int i = 0; i < KB; i++) wc[i] = *(const float4*)(wbase + i * DD);

        #pragma unroll 2
        for (int kb = 0; kb < DD / KB; kb++) {
            const float* wnx = wbase + ((kb + 1 < DD / KB) ? (kb + 1) : kb) * (KB * DD);
            #pragma unroll
            for (int i = 0; i < KB; i++) wn[i] = *(const float4*)(wnx + i * DD);

            const float* abase = cur + (kb * KB) * HS + r0;
            #pragma unroll
            for (int i = 0; i < KB; i++) {
                ulonglong2 aA = *(const ulonglong2*)(abase + i * HS);     // rows r0..r0+3
                ulonglong2 aB = *(const ulonglong2*)(abase + i * HS + 4); // rows r0+4..r0+7
                unsigned long long w0 = pack2(wc[i].x, wc[i].x);
                unsigned long long w1 = pack2(wc[i].y, wc[i].y);
                unsigned long long w2 = pack2(wc[i].z, wc[i].z);
                unsigned long long w3 = pack2(wc[i].w, wc[i].w);
                fma2(acc[0][0], aA.x, w0); fma2(acc[0][1], aA.x, w1);
                fma2(acc[0][2], aA.x, w2); fma2(acc[0][3], aA.x, w3);
                fma2(acc[1][0], aA.y, w0); fma2(acc[1][1], aA.y, w1);
                fma2(acc[1][2], aA.y, w2); fma2(acc[1][3], aA.y, w3);
                fma2(acc[2][0], aB.x, w0); fma2(acc[2][1], aB.x, w1);
                fma2(acc[2][2], aB.x, w2); fma2(acc[2][3], aB.x, w3);
                fma2(acc[3][0], aB.y, w0); fma2(acc[3][1], aB.y, w1);
                fma2(acc[3][2], aB.y, w2); fma2(acc[3][3], aB.y, w3);
            }
            #pragma unroll
            for (int i = 0; i < KB; i++) wc[i] = wn[i];
        }

        // ---- bias + tanh (register-only) ----
        float hv[4][8];   // hv[c][rr] : col c, rows r0..r0+7
        #pragma unroll
        for (int c = 0; c < 4; c++) {
            #pragma unroll
            for (int p = 0; p < 4; p++) {
                fma2(acc[p][c], bp[c], ONE2);      // acc += bias
                float2 v = unpack2(acc[p][c]);
                hv[c][2 * p]     = fast_tanh(v.x);
                hv[c][2 * p + 1] = fast_tanh(v.y);
            }
        }

        // ---- commit h(t+1) into NEXT buffer ----
        #pragma unroll
        for (int c = 0; c < 4; c++) {
            float* dst = nxt + (j0 + c) * HS + r0;
            *(float4*)(dst)     = make_float4(hv[c][0], hv[c][1], hv[c][2], hv[c][3]);
            *(float4*)(dst + 4) = make_float4(hv[c][4], hv[c][5], hv[c][6], hv[c][7]);
        }
        __syncthreads();   // nxt complete AND all reads of cur done (one barrier/step)
    }

    // ---- classifier: final h is in buf0 (t=127 wrote nxt=buf0) ----
    if (tid < ROWS * CC) {
        int r = tid / CC;
        int c = tid % CC;
        float s = b_cls[c];
        const float* wc2 = W_cls + c * DD;
        #pragma unroll 8
        for (int d = 0; d < DD; d++) {
            s += buf0[d * HS + r] * wc2[d];
        }
        out[(size_t)(row0 + r) * CC + c] = s;
    }
}

extern "C" void kernel_launch(void* const* d_in, const int* in_sizes, int n_in,
                              void* d_out, int out_size) {
    const int* x         = (const int*)d_in[0];   // int32
    const float* emb     = (const float*)d_in[1];
    const float* W_ih    = (const float*)d_in[2];
    const float* W_hh    = (const float*)d_in[3];
    const float* b_ih    = (const float*)d_in[4];
    const float* b_hh    = (const float*)d_in[5];
    const float* W_cls   = (const float*)d_in[6];
    const float* b_cls   = (const float*)d_in[7];
    float* out = (float*)d_out;

    (void)in_sizes; (void)n_in; (void)out_size;

    cudaFuncSetAttribute(rnn_kernel, cudaFuncAttributeMaxDynamicSharedMemorySize, SMEM_BYTES);

    prep_kernel<<<DD, DD>>>(W_ih, W_hh, b_ih, b_hh);
    egemm_kernel<<<PGRID, NTHREADS>>>(emb);
    rnn_kernel<<<NGRID, NTHREADS, SMEM_BYTES>>>(x, W_cls, b_cls, out);
}

// round 12
// speedup vs baseline: 2.2053x; 1.0671x over previous
#include <cuda_runtime.h>
#include <cstdint>
#include <cstddef>

// Problem constants
#define VOCAB 50000
#define BB 4096
#define SS 128
#define DD 256
#define CC 5

#define ROWS 32            // batch rows per CTA
#define NTHREADS 256       // 8 warps = 4 row-groups (8 rows) x 2 j-halves (128 cols)
#define NGRID (BB / ROWS)  // 128 CTAs
#define HS 36              // padded stride (floats) of k-major SMEM h tiles
#define KB 8               // k-block size for streamed weight pipeline
#define WC 144             // weight k-rows cached in SMEM (rest streamed from L2)
#define KSTREAM (DD - WC)  // 112 streamed k-rows
#define NKB (KSTREAM / KB) // 14 blocks

// Device globals (static allocation only).
__device__ __align__(16) float g_Whh_t[DD * DD];   // Whh_t[k][j] = W_hh[j][k]
__device__ __align__(16) float g_Wih_t[DD * DD];   // Wih_t[k][j] = W_ih[j][k]
__device__ __align__(16) float g_bias[DD];         // b_ih + b_hh
__device__ __align__(16) float g_E2[VOCAB * DD];   // E' = emb @ W_ih^T  (51.2 MB)

// ---------- f32x2 packed-FMA helpers (sm_103a) ----------
__device__ __forceinline__ unsigned long long pack2(float x, float y) {
    unsigned long long r;
    asm("mov.b64 %0, {%1,%2};" : "=l"(r) : "f"(x), "f"(y));
    return r;
}
__device__ __forceinline__ void fma2(unsigned long long& d, unsigned long long a, unsigned long long b) {
    asm("fma.rn.f32x2 %0, %1, %2, %0;" : "+l"(d) : "l"(a), "l"(b));
}
__device__ __forceinline__ float2 unpack2(unsigned long long v) {
    float2 r;
    asm("mov.b64 {%0,%1}, %2;" : "=f"(r.x), "=f"(r.y) : "l"(v));
    return r;
}

// Fast accurate tanh: 1 - 2/(e^{2x}+1). abs err ~1e-6, far inside 1e-3 budget.
__device__ __forceinline__ float fast_tanh(float x) {
    x = fminf(fmaxf(x, -10.0f), 10.0f);
    float e = __expf(2.0f * x);
    return 1.0f - __fdividef(2.0f, e + 1.0f);
}

// ---------- prep1: transpose weights, fuse biases ----------
__global__ void prep_kernel(const float* __restrict__ W_ih,
                            const float* __restrict__ W_hh,
                            const float* __restrict__ b_ih,
                            const float* __restrict__ b_hh) {
    int k = blockIdx.x;   // 0..255
    int j = threadIdx.x;  // 0..255
    g_Whh_t[k * DD + j] = W_hh[j * DD + k];
    g_Wih_t[k * DD + j] = W_ih[j * DD + k];
    if (k == 0) g_bias[j] = b_ih[j] + b_hh[j];
}

// ---------- prep2: E' = emb @ W_ih^T  ([VOCAB,256] x [256,256]) ----------
#define PGRID ((VOCAB + ROWS - 1) / ROWS)   // 1563

__global__ void __launch_bounds__(NTHREADS, 1)
egemm_kernel(const float* __restrict__ emb) {
    __shared__ float xe_s[DD * HS];   // k-major emb tile

    const int tid  = threadIdx.x;
    const int lane = tid & 31;
    const int warp = tid >> 5;
    const int v0   = blockIdx.x * ROWS;

    const int r0 = (warp >> 1) * 8;
    const int j0 = (warp & 1) * 128 + lane * 4;
    const int g_row = tid >> 3;
    const int g_sub = tid & 7;

    // gather emb tile (clamp OOB rows to 0; emb[0] is the zero pad row anyway)
    {
        int v = v0 + g_row;
        if (v >= VOCAB) v = 0;
        const float* erow = emb + (size_t)v * DD;
        #pragma unroll
        for (int i = 0; i < 8; i++) {
            float4 vv = *(const float4*)(erow + i * 32 + g_sub * 4);
            int c0 = i * 32 + g_sub * 4;
            xe_s[(c0 + 0) * HS + g_row] = vv.x;
            xe_s[(c0 + 1) * HS + g_row] = vv.y;
            xe_s[(c0 + 2) * HS + g_row] = vv.z;
            xe_s[(c0 + 3) * HS + g_row] = vv.w;
        }
    }
    __syncthreads();

    unsigned long long acc[4][4];
    const unsigned long long z = pack2(0.0f, 0.0f);
    #pragma unroll
    for (int p = 0; p < 4; p++) {
        acc[p][0] = z; acc[p][1] = z; acc[p][2] = z; acc[p][3] = z;
    }

    const float* wbase = g_Wih_t + j0;
    float4 wcv[KB], wnv[KB];
    #pragma unroll
    for (int i = 0; i < KB; i++) wcv[i] = *(const float4*)(wbase + i * DD);

    #pragma unroll 2
    for (int kb = 0; kb < DD / KB; kb++) {
        const float* wnx = wbase + ((kb + 1 < DD / KB) ? (kb + 1) : kb) * (KB * DD);
        #pragma unroll
        for (int i = 0; i < KB; i++) wnv[i] = *(const float4*)(wnx + i * DD);

        const float* abase = xe_s + (kb * KB) * HS + r0;
        #pragma unroll
        for (int i = 0; i < KB; i++) {
            ulonglong2 aA = *(const ulonglong2*)(abase + i * HS);
            ulonglong2 aB = *(const ulonglong2*)(abase + i * HS + 4);
            unsigned long long w0 = pack2(wcv[i].x, wcv[i].x);
            unsigned long long w1 = pack2(wcv[i].y, wcv[i].y);
            unsigned long long w2 = pack2(wcv[i].z, wcv[i].z);
            unsigned long long w3 = pack2(wcv[i].w, wcv[i].w);
            fma2(acc[0][0], aA.x, w0); fma2(acc[0][1], aA.x, w1);
            fma2(acc[0][2], aA.x, w2); fma2(acc[0][3], aA.x, w3);
            fma2(acc[1][0], aA.y, w0); fma2(acc[1][1], aA.y, w1);
            fma2(acc[1][2], aA.y, w2); fma2(acc[1][3], aA.y, w3);
            fma2(acc[2][0], aB.x, w0); fma2(acc[2][1], aB.x, w1);
            fma2(acc[2][2], aB.x, w2); fma2(acc[2][3], aB.x, w3);
            fma2(acc[3][0], aB.y, w0); fma2(acc[3][1], aB.y, w1);
            fma2(acc[3][2], aB.y, w2); fma2(acc[3][3], aB.y, w3);
        }
        #pragma unroll
        for (int i = 0; i < KB; i++) wcv[i] = wnv[i];
    }

    #pragma unroll
    for (int p = 0; p < 4; p++) {
        float2 v0c = unpack2(acc[p][0]);
        float2 v1c = unpack2(acc[p][1]);
        float2 v2c = unpack2(acc[p][2]);
        float2 v3c = unpack2(acc[p][3]);
        int va = v0 + r0 + 2 * p;
        int vb = va + 1;
        if (va < VOCAB)
            *(float4*)(g_E2 + (size_t)va * DD + j0) = make_float4(v0c.x, v1c.x, v2c.x, v3c.x);
        if (vb < VOCAB)
            *(float4*)(g_E2 + (size_t)vb * DD + j0) = make_float4(v0c.y, v1c.y, v2c.y, v3c.y);
    }
}

// ---------- fused persistent RNN kernel ----------
// SMEM (floats):
//   ws   [WC][DD]  : first 144 k-rows of Whh^T, resident all 128 steps (144 KB)
//   buf0/buf1 [DD][HS] : k-major hidden-state double buffer (73.7 KB)
#define BUF_FLOATS (DD * HS)
#define SMEM_FLOATS (WC * DD + 2 * BUF_FLOATS)
#define SMEM_BYTES  (SMEM_FLOATS * 4)

__global__ void __launch_bounds__(NTHREADS, 1)
rnn_kernel(const int* __restrict__ x,          // int32 (JAX x64-disabled)
           const float* __restrict__ W_cls,
           const float* __restrict__ b_cls,
           float* __restrict__ out) {
    extern __shared__ float smem[];
    float* ws    = smem;                        // WC*DD
    float* buf0  = smem + WC * DD;              // DD*HS
    float* buf1  = buf0 + BUF_FLOATS;           // DD*HS

    const int tid  = threadIdx.x;
    const int lane = tid & 31;
    const int warp = tid >> 5;
    const int row0 = blockIdx.x * ROWS;

    // warp tile: 8 rows x 128 cols; thread tile: 8 rows x 4 cols (16 fma2/k)
    const int r0 = (warp >> 1) * 8;                  // 0,8,16,24
    const int j0 = (warp & 1) * 128 + lane * 4;

    // ---- one-time init: fill weight cache + zero h in buf0 ----
    for (int idx = tid * 4; idx < WC * DD; idx += NTHREADS * 4)
        *(float4*)(ws + idx) = *(const float4*)(g_Whh_t + idx);
    for (int idx = tid; idx < BUF_FLOATS; idx += NTHREADS) buf0[idx] = 0.0f;

    // bias pairs + unit multiplier
    const float4 b4 = *(const float4*)(g_bias + j0);
    unsigned long long bp[4];
    bp[0] = pack2(b4.x, b4.x);
    bp[1] = pack2(b4.y, b4.y);
    bp[2] = pack2(b4.z, b4.z);
    bp[3] = pack2(b4.w, b4.w);
    const unsigned long long ONE2 = pack2(1.0f, 1.0f);

    // token base for this thread's 8 rows
    const int* xrow = x + (size_t)(row0 + r0) * SS;

    // ---- prologue: gather E'[tok(0)] for this thread's 8 rows x 4 cols ----
    float4 xr[8];
    #pragma unroll
    for (int i = 0; i < 8; i++) {
        int tokr = xrow[i * SS + 0];
        xr[i] = *(const float4*)(g_E2 + (size_t)tokr * DD + j0);
    }

    __syncthreads();   // ws + h-zero visible

    const float* wstream = g_Whh_t + WC * DD + j0;   // streamed half base

    for (int t = 0; t < SS; t++) {
        float* cur = (t & 1) ? buf1 : buf0;
        float* nxt = (t & 1) ? buf0 : buf1;

        // ---- acc init from E'[tok(t)] (xr consumed, regs freed) ----
        unsigned long long acc[4][4];
        #pragma unroll
        for (int p = 0; p < 4; p++) {
            acc[p][0] = pack2(xr[2 * p].x, xr[2 * p + 1].x);
            acc[p][1] = pack2(xr[2 * p].y, xr[2 * p + 1].y);
            acc[p][2] = pack2(xr[2 * p].z, xr[2 * p + 1].z);
            acc[p][3] = pack2(xr[2 * p].w, xr[2 * p + 1].w);
        }

        // ---- prefetch tokens + E'[tok(t+1)] (hidden under the GEMM) ----
        {
            int tn = (t + 1 < SS) ? (t + 1) : t;
            int tk[8];
            #pragma unroll
            for (int i = 0; i < 8; i++) tk[i] = xrow[i * SS + tn];
            #pragma unroll
            for (int i = 0; i < 8; i++)
                xr[i] = *(const float4*)(g_E2 + (size_t)tk[i] * DD + j0);
        }

        // ---- phase A: cached weights (SMEM), k = 0..WC-1 ----
        #pragma unroll 8
        for (int k = 0; k < WC; k++) {
            float4 w = *(const float4*)(ws + (k << 8) + j0);          // LDS.128, conflict-free
            ulonglong2 aA = *(const ulonglong2*)(cur + k * HS + r0);
            ulonglong2 aB = *(const ulonglong2*)(cur + k * HS + r0 + 4);
            unsigned long long w0 = pack2(w.x, w.x);
            unsigned long long w1 = pack2(w.y, w.y);
            unsigned long long w2 = pack2(w.z, w.z);
            unsigned long long w3 = pack2(w.w, w.w);
            fma2(acc[0][0], aA.x, w0); fma2(acc[0][1], aA.x, w1);
            fma2(acc[0][2], aA.x, w2); fma2(acc[0][3], aA.x, w3);
            fma2(acc[1][0], aA.y, w0); fma2(acc[1][1], aA.y, w1);
            fma2(acc[1][2], aA.y, w2); fma2(acc[1][3], aA.y, w3);
            fma2(acc[2][0], aB.x, w0); fma2(acc[2][1], aB.x, w1);
            fma2(acc[2][2], aB.x, w2); fma2(acc[2][3], aB.x, w3);
            fma2(acc[3][0], aB.y, w0); fma2(acc[3][1], aB.y, w1);
            fma2(acc[3][2], aB.y, w2); fma2(acc[3][3], aB.y, w3);
        }

        // ---- phase B: streamed weights (L2), k = WC..255, block-pipelined ----
        {
            float4 wcv[KB], wnv[KB];
            #pragma unroll
            for (int i = 0; i < KB; i++) wcv[i] = *(const float4*)(wstream + i * DD);

            #pragma unroll 2
            for (int kb = 0; kb < NKB; kb++) {
                const float* wnx = wstream + ((kb + 1 < NKB) ? (kb + 1) : kb) * (KB * DD);
                #pragma unroll
                for (int i = 0; i < KB; i++) wnv[i] = *(const float4*)(wnx + i * DD);

                const float* abase = cur + (WC + kb * KB) * HS + r0;
                #pragma unroll
                for (int i = 0; i < KB; i++) {
                    ulonglong2 aA = *(const ulonglong2*)(abase + i * HS);
                    ulonglong2 aB = *(const ulonglong2*)(abase + i * HS + 4);
                    unsigned long long w0 = pack2(wcv[i].x, wcv[i].x);
                    unsigned long long w1 = pack2(wcv[i].y, wcv[i].y);
                    unsigned long long w2 = pack2(wcv[i].z, wcv[i].z);
                    unsigned long long w3 = pack2(wcv[i].w, wcv[i].w);
                    fma2(acc[0][0], aA.x, w0); fma2(acc[0][1], aA.x, w1);
                    fma2(acc[0][2], aA.x, w2); fma2(acc[0][3], aA.x, w3);
                    fma2(acc[1][0], aA.y, w0); fma2(acc[1][1], aA.y, w1);
                    fma2(acc[1][2], aA.y, w2); fma2(acc[1][3], aA.y, w3);
                    fma2(acc[2][0], aB.x, w0); fma2(acc[2][1], aB.x, w1);
                    fma2(acc[2][2], aB.x, w2); fma2(acc[2][3], aB.x, w3);
                    fma2(acc[3][0], aB.y, w0); fma2(acc[3][1], aB.y, w1);
                    fma2(acc[3][2], aB.y, w2); fma2(acc[3][3], aB.y, w3);
                }
                #pragma unroll
                for (int i = 0; i < KB; i++) wcv[i] = wnv[i];
            }
        }

        // ---- bias + tanh (register-only) ----
        float hv[4][8];   // hv[c][rr] : col c, rows r0..r0+7
        #pragma unroll
        for (int c = 0; c < 4; c++) {
            #pragma unroll
            for (int p = 0; p < 4; p++) {
                fma2(acc[p][c], bp[c], ONE2);      // acc += bias
                float2 v = unpack2(acc[p][c]);
                hv[c][2 * p]     = fast_tanh(v.x);
                hv[c][2 * p + 1] = fast_tanh(v.y);
            }
        }

        // ---- commit h(t+1) into NEXT buffer ----
        #pragma unroll
        for (int c = 0; c < 4; c++) {
            float* dst = nxt + (j0 + c) * HS + r0;
            *(float4*)(dst)     = make_float4(hv[c][0], hv[c][1], hv[c][2], hv[c][3]);
            *(float4*)(dst + 4) = make_float4(hv[c][4], hv[c][5], hv[c][6], hv[c][7]);
        }
        __syncthreads();   // nxt complete AND all reads of cur done (one barrier/step)
    }

    // ---- classifier: final h is in buf0 (t=127 wrote nxt=buf0) ----
    if (tid < ROWS * CC) {
        int r = tid / CC;
        int c = tid % CC;
        float s = b_cls[c];
        const float* wc2 = W_cls + c * DD;
        #pragma unroll 8
        for (int d = 0; d < DD; d++) {
            s += buf0[d * HS + r] * wc2[d];
        }
        out[(size_t)(row0 + r) * CC + c] = s;
    }
}

extern "C" void kernel_launch(void* const* d_in, const int* in_sizes, int n_in,
                              void* d_out, int out_size) {
    const int* x         = (const int*)d_in[0];   // int32
    const float* emb     = (const float*)d_in[1];
    const float* W_ih    = (const float*)d_in[2];
    const float* W_hh    = (const float*)d_in[3];
    const float* b_ih    = (const float*)d_in[4];
    const float* b_hh    = (const float*)d_in[5];
    const float* W_cls   = (const float*)d_in[6];
    const float* b_cls   = (const float*)d_in[7];
    float* out = (float*)d_out;

    (void)in_sizes; (void)n_in; (void)out_size;

    cudaFuncSetAttribute(rnn_kernel, cudaFuncAttributeMaxDynamicSharedMemorySize, SMEM_BYTES);

    prep_kernel<<<DD, DD>>>(W_ih, W_hh, b_ih, b_hh);
    egemm_kernel<<<PGRID, NTHREADS>>>(emb);
    rnn_kernel<<<NGRID, NTHREADS, SMEM_BYTES>>>(x, W_cls, b_cls, out);
}

// round 13
// speedup vs baseline: 2.4387x; 1.1059x over previous
#include <cuda_runtime.h>
#include <cstdint>
#include <cstddef>

// Problem constants
#define VOCAB 50000
#define BB 4096
#define SS 128
#define DD 256
#define CC 5

#define ROWS 32            // batch rows per CTA
#define NTHREADS 256       // 8 warps
#define NGRID (BB / ROWS)  // 128 CTAs
#define HS 36              // padded stride (floats) of k-major SMEM tiles
#define KB 8               // k-block size for streamed weight pipeline
#define WC 152             // weight k-rows cached in SMEM (rest streamed from L2)
#define KSTREAM (DD - WC)  // 104 streamed k-rows
#define NKB (KSTREAM / KB) // 13 blocks

// Device globals (static allocation only).
__device__ __align__(16) float g_Whh_t[DD * DD];   // Whh_t[k][j] = W_hh[j][k]
__device__ __align__(16) float g_Wih_t[DD * DD];   // Wih_t[k][j] = W_ih[j][k]
__device__ __align__(16) float g_bias[DD];         // b_ih + b_hh
__device__ __align__(16) float g_E2[VOCAB * DD];   // E' = emb @ W_ih^T  (51.2 MB)

// ---------- f32x2 packed-FMA helpers (sm_103a) ----------
__device__ __forceinline__ unsigned long long pack2(float x, float y) {
    unsigned long long r;
    asm("mov.b64 %0, {%1,%2};" : "=l"(r) : "f"(x), "f"(y));
    return r;
}
__device__ __forceinline__ void fma2(unsigned long long& d, unsigned long long a, unsigned long long b) {
    asm("fma.rn.f32x2 %0, %1, %2, %0;" : "+l"(d) : "l"(a), "l"(b));
}
__device__ __forceinline__ float2 unpack2(unsigned long long v) {
    float2 r;
    asm("mov.b64 {%0,%1}, %2;" : "=f"(r.x), "=f"(r.y) : "l"(v));
    return r;
}

// Fast accurate tanh: 1 - 2/(e^{2x}+1). abs err ~1e-6, far inside 1e-3 budget.
__device__ __forceinline__ float fast_tanh(float x) {
    x = fminf(fmaxf(x, -10.0f), 10.0f);
    float e = __expf(2.0f * x);
    return 1.0f - __fdividef(2.0f, e + 1.0f);
}

// ---------- prep1: transpose weights, fuse biases ----------
__global__ void prep_kernel(const float* __restrict__ W_ih,
                            const float* __restrict__ W_hh,
                            const float* __restrict__ b_ih,
                            const float* __restrict__ b_hh) {
    int k = blockIdx.x;   // 0..255
    int j = threadIdx.x;  // 0..255
    g_Whh_t[k * DD + j] = W_hh[j * DD + k];
    g_Wih_t[k * DD + j] = W_ih[j * DD + k];
    if (k == 0) g_bias[j] = b_ih[j] + b_hh[j];
}

// ---------- prep2: E' = emb @ W_ih^T, persistent weight-resident ----------
// grid = 296 = 148 parts x 2 j-halves. Each CTA pins its 128-col weight slice
// in SMEM (128 KB) once, then loops vocab tiles (32 rows each) over its part.
#define NTILES ((VOCAB + ROWS - 1) / ROWS)   // 1563
#define EG_GRID 296
#define EG_JC 128                             // cols per CTA

// SMEM: wsW [256][128] (128 KB) + xe_s [256][HS] (36.9 KB)
#define EG_SMEM_FLOATS (DD * EG_JC + DD * HS)
#define EG_SMEM_BYTES  (EG_SMEM_FLOATS * 4)

__global__ void __launch_bounds__(NTHREADS, 1)
egemm_kernel(const float* __restrict__ emb) {
    extern __shared__ float esm[];
    float* wsW  = esm;                 // DD*EG_JC, k-major rows of 128 cols
    float* xe_s = esm + DD * EG_JC;    // DD*HS

    const int tid  = threadIdx.x;
    const int lane = tid & 31;
    const int warp = tid >> 5;
    const int part = blockIdx.x >> 1;        // 0..147
    const int jh   = blockIdx.x & 1;         // 0/1
    const int jbase = jh * EG_JC;

    // warp tile: 8 rows x 64 cols; thread: 8 rows x 2 cols (8 fma2/k)
    const int r0 = (warp >> 1) * 8;
    const int jj = (warp & 1) * 64 + lane * 2;   // col within 128-slice

    const int g_row = tid >> 3;     // 0..31 (gather: 8 threads/row)
    const int g_sub = tid & 7;

    // ---- one-time: load this CTA's weight slice into SMEM ----
    for (int idx = tid * 4; idx < DD * EG_JC; idx += NTHREADS * 4) {
        int k = idx >> 7;           // /128
        int c = idx & 127;
        *(float4*)(wsW + idx) = *(const float4*)(g_Wih_t + k * DD + jbase + c);
    }
    __syncthreads();

    for (int tile = part; tile < NTILES; tile += 148) {
        const int v0 = tile * ROWS;

        // ---- gather emb tile (k-major); clamp OOB rows to row 0 ----
        {
            int v = v0 + g_row;
            if (v >= VOCAB) v = 0;
            const float* erow = emb + (size_t)v * DD;
            #pragma unroll
            for (int i = 0; i < 8; i++) {
                float4 vv = *(const float4*)(erow + i * 32 + g_sub * 4);
                int c0 = i * 32 + g_sub * 4;
                xe_s[(c0 + 0) * HS + g_row] = vv.x;
                xe_s[(c0 + 1) * HS + g_row] = vv.y;
                xe_s[(c0 + 2) * HS + g_row] = vv.z;
                xe_s[(c0 + 3) * HS + g_row] = vv.w;
            }
        }
        __syncthreads();

        // ---- GEMM: all weights from SMEM ----
        unsigned long long acc[4][2];
        const unsigned long long z = pack2(0.0f, 0.0f);
        #pragma unroll
        for (int p = 0; p < 4; p++) { acc[p][0] = z; acc[p][1] = z; }

        #pragma unroll 8
        for (int k = 0; k < DD; k++) {
            float2 w = *(const float2*)(wsW + (k << 7) + jj);            // LDS.64
            ulonglong2 aA = *(const ulonglong2*)(xe_s + k * HS + r0);
            ulonglong2 aB = *(const ulonglong2*)(xe_s + k * HS + r0 + 4);
            unsigned long long w0 = pack2(w.x, w.x);
            unsigned long long w1 = pack2(w.y, w.y);
            fma2(acc[0][0], aA.x, w0); fma2(acc[0][1], aA.x, w1);
            fma2(acc[1][0], aA.y, w0); fma2(acc[1][1], aA.y, w1);
            fma2(acc[2][0], aB.x, w0); fma2(acc[2][1], aB.x, w1);
            fma2(acc[3][0], aB.y, w0); fma2(acc[3][1], aB.y, w1);
        }

        // ---- epilogue: write E2[v][jbase+jj .. +1] ----
        #pragma unroll
        for (int p = 0; p < 4; p++) {
            float2 c0 = unpack2(acc[p][0]);   // (row 2p, row 2p+1) col jj
            float2 c1 = unpack2(acc[p][1]);   // col jj+1
            int va = v0 + r0 + 2 * p;
            int vb = va + 1;
            if (va < VOCAB)
                *(float2*)(g_E2 + (size_t)va * DD + jbase + jj) = make_float2(c0.x, c1.x);
            if (vb < VOCAB)
                *(float2*)(g_E2 + (size_t)vb * DD + jbase + jj) = make_float2(c0.y, c1.y);
        }
        __syncthreads();   // xe_s reads done before next tile's gather
    }
}

// ---------- fused persistent RNN kernel ----------
// SMEM (floats):
//   ws   [WC][DD]  : first 152 k-rows of Whh^T, resident all 128 steps
//   buf0/buf1 [DD][HS] : k-major hidden-state double buffer
#define BUF_FLOATS (DD * HS)
#define SMEM_FLOATS (WC * DD + 2 * BUF_FLOATS)
#define SMEM_BYTES  (SMEM_FLOATS * 4)

__global__ void __launch_bounds__(NTHREADS, 1)
rnn_kernel(const int* __restrict__ x,          // int32 (JAX x64-disabled)
           const float* __restrict__ W_cls,
           const float* __restrict__ b_cls,
           float* __restrict__ out) {
    extern __shared__ float smem[];
    float* ws    = smem;                        // WC*DD
    float* buf0  = smem + WC * DD;              // DD*HS
    float* buf1  = buf0 + BUF_FLOATS;           // DD*HS

    const int tid  = threadIdx.x;
    const int lane = tid & 31;
    const int warp = tid >> 5;
    const int row0 = blockIdx.x * ROWS;

    // warp tile: 8 rows x 128 cols; thread tile: 8 rows x 4 cols (16 fma2/k)
    const int r0 = (warp >> 1) * 8;                  // 0,8,16,24
    const int j0 = (warp & 1) * 128 + lane * 4;

    // ---- one-time init: fill weight cache + zero h in buf0 ----
    for (int idx = tid * 4; idx < WC * DD; idx += NTHREADS * 4)
        *(float4*)(ws + idx) = *(const float4*)(g_Whh_t + idx);
    for (int idx = tid; idx < BUF_FLOATS; idx += NTHREADS) buf0[idx] = 0.0f;

    // bias pairs + unit multiplier
    const float4 b4 = *(const float4*)(g_bias + j0);
    unsigned long long bp[4];
    bp[0] = pack2(b4.x, b4.x);
    bp[1] = pack2(b4.y, b4.y);
    bp[2] = pack2(b4.z, b4.z);
    bp[3] = pack2(b4.w, b4.w);
    const unsigned long long ONE2 = pack2(1.0f, 1.0f);

    // token base for this thread's 8 rows
    const int* xrow = x + (size_t)(row0 + r0) * SS;

    // ---- prologue: gather E'[tok(0)] for this thread's 8 rows x 4 cols ----
    float4 xr[8];
    #pragma unroll
    for (int i = 0; i < 8; i++) {
        int tokr = xrow[i * SS + 0];
        xr[i] = *(const float4*)(g_E2 + (size_t)tokr * DD + j0);
    }

    __syncthreads();   // ws + h-zero visible

    const float* wstream = g_Whh_t + WC * DD + j0;   // streamed tail base

    for (int t = 0; t < SS; t++) {
        float* cur = (t & 1) ? buf1 : buf0;
        float* nxt = (t & 1) ? buf0 : buf1;

        // ---- acc init from E'[tok(t)] (xr consumed, regs freed) ----
        unsigned long long acc[4][4];
        #pragma unroll
        for (int p = 0; p < 4; p++) {
            acc[p][0] = pack2(xr[2 * p].x, xr[2 * p + 1].x);
            acc[p][1] = pack2(xr[2 * p].y, xr[2 * p + 1].y);
            acc[p][2] = pack2(xr[2 * p].z, xr[2 * p + 1].z);
            acc[p][3] = pack2(xr[2 * p].w, xr[2 * p + 1].w);
        }

        // ---- HOISTED: phase-B first weight block (static addr; latency hides
        //      under all of phase A) ----
        float4 wcv[KB], wnv[KB];
        #pragma unroll
        for (int i = 0; i < KB; i++) wcv[i] = *(const float4*)(wstream + i * DD);

        // ---- prefetch tokens + E'[tok(t+1)] (hidden under the GEMM) ----
        {
            int tn = (t + 1 < SS) ? (t + 1) : t;
            int tk[8];
            #pragma unroll
            for (int i = 0; i < 8; i++) tk[i] = xrow[i * SS + tn];
            #pragma unroll
            for (int i = 0; i < 8; i++)
                xr[i] = *(const float4*)(g_E2 + (size_t)tk[i] * DD + j0);
        }

        // ---- phase A: cached weights (SMEM), k = 0..WC-1 ----
        #pragma unroll 8
        for (int k = 0; k < WC; k++) {
            float4 w = *(const float4*)(ws + (k << 8) + j0);          // LDS.128
            ulonglong2 aA = *(const ulonglong2*)(cur + k * HS + r0);
            ulonglong2 aB = *(const ulonglong2*)(cur + k * HS + r0 + 4);
            unsigned long long w0 = pack2(w.x, w.x);
            unsigned long long w1 = pack2(w.y, w.y);
            unsigned long long w2 = pack2(w.z, w.z);
            unsigned long long w3 = pack2(w.w, w.w);
            fma2(acc[0][0], aA.x, w0); fma2(acc[0][1], aA.x, w1);
            fma2(acc[0][2], aA.x, w2); fma2(acc[0][3], aA.x, w3);
            fma2(acc[1][0], aA.y, w0); fma2(acc[1][1], aA.y, w1);
            fma2(acc[1][2], aA.y, w2); fma2(acc[1][3], aA.y, w3);
            fma2(acc[2][0], aB.x, w0); fma2(acc[2][1], aB.x, w1);
            fma2(acc[2][2], aB.x, w2); fma2(acc[2][3], aB.x, w3);
            fma2(acc[3][0], aB.y, w0); fma2(acc[3][1], aB.y, w1);
            fma2(acc[3][2], aB.y, w2); fma2(acc[3][3], aB.y, w3);
        }

        // ---- phase B: streamed weights (L2), k = WC..255, block-pipelined ----
        #pragma unroll 2
        for (int kb = 0; kb < NKB; kb++) {
            const float* wnx = wstream + ((kb + 1 < NKB) ? (kb + 1) : kb) * (KB * DD);
            #pragma unroll
            for (int i = 0; i < KB; i++) wnv[i] = *(const float4*)(wnx + i * DD);

            const float* abase = cur + (WC + kb * KB) * HS + r0;
            #pragma unroll
            for (int i = 0; i < KB; i++) {
                ulonglong2 aA = *(const ulonglong2*)(abase + i * HS);
                ulonglong2 aB = *(const ulonglong2*)(abase + i * HS + 4);
                unsigned long long w0 = pack2(wcv[i].x, wcv[i].x);
                unsigned long long w1 = pack2(wcv[i].y, wcv[i].y);
                unsigned long long w2 = pack2(wcv[i].z, wcv[i].z);
                unsigned long long w3 = pack2(wcv[i].w, wcv[i].w);
                fma2(acc[0][0], aA.x, w0); fma2(acc[0][1], aA.x, w1);
                fma2(acc[0][2], aA.x, w2); fma2(acc[0][3], aA.x, w3);
                fma2(acc[1][0], aA.y, w0); fma2(acc[1][1], aA.y, w1);
                fma2(acc[1][2], aA.y, w2); fma2(acc[1][3], aA.y, w3);
                fma2(acc[2][0], aB.x, w0); fma2(acc[2][1], aB.x, w1);
                fma2(acc[2][2], aB.x, w2); fma2(acc[2][3], aB.x, w3);
                fma2(acc[3][0], aB.y, w0); fma2(acc[3][1], aB.y, w1);
                fma2(acc[3][2], aB.y, w2); fma2(acc[3][3], aB.y, w3);
            }
            #pragma unroll
            for (int i = 0; i < KB; i++) wcv[i] = wnv[i];
        }

        // ---- bias + tanh (register-only) ----
        float hv[4][8];   // hv[c][rr] : col c, rows r0..r0+7
        #pragma unroll
        for (int c = 0; c < 4; c++) {
            #pragma unroll
            for (int p = 0; p < 4; p++) {
                fma2(acc[p][c], bp[c], ONE2);      // acc += bias
                float2 v = unpack2(acc[p][c]);
                hv[c][2 * p]     = fast_tanh(v.x);
                hv[c][2 * p + 1] = fast_tanh(v.y);
            }
        }

        // ---- commit h(t+1) into NEXT buffer ----
        #pragma unroll
        for (int c = 0; c < 4; c++) {
            float* dst = nxt + (j0 + c) * HS + r0;
            *(float4*)(dst)     = make_float4(hv[c][0], hv[c][1], hv[c][2], hv[c][3]);
            *(float4*)(dst + 4) = make_float4(hv[c][4], hv[c][5], hv[c][6], hv[c][7]);
        }
        __syncthreads();   // nxt complete AND all reads of cur done (one barrier/step)
    }

    // ---- classifier: final h is in buf0 (t=127 wrote nxt=buf0) ----
    if (tid < ROWS * CC) {
        int r = tid / CC;
        int c = tid % CC;
        float s = b_cls[c];
        const float* wc2 = W_cls + c * DD;
        #pragma unroll 8
        for (int d = 0; d < DD; d++) {
            s += buf0[d * HS + r] * wc2[d];
        }
        out[(size_t)(row0 + r) * CC + c] = s;
    }
}

extern "C" void kernel_launch(void* const* d_in, const int* in_sizes, int n_in,
                              void* d_out, int out_size) {
    const int* x         = (const int*)d_in[0];   // int32
    const float* emb     = (const float*)d_in[1];
    const float* W_ih    = (const float*)d_in[2];
    const float* W_hh    = (const float*)d_in[3];
    const float* b_ih    = (const float*)d_in[4];
    const float* b_hh    = (const float*)d_in[5];
    const float* W_cls   = (const float*)d_in[6];
    const float* b_cls   = (const float*)d_in[7];
    float* out = (float*)d_out;

    (void)in_sizes; (void)n_in; (void)out_size;

    cudaFuncSetAttribute(rnn_kernel, cudaFuncAttributeMaxDynamicSharedMemorySize, SMEM_BYTES);
    cudaFuncSetAttribute(egemm_kernel, cudaFuncAttributeMaxDynamicSharedMemorySize, EG_SMEM_BYTES);

    prep_kernel<<<DD, DD>>>(W_ih, W_hh, b_ih, b_hh);
    egemm_kernel<<<EG_GRID, NTHREADS, EG_SMEM_BYTES>>>(emb);
    rnn_kernel<<<NGRID, NTHREADS, SMEM_BYTES>>>(x, W_cls, b_cls, out);
}